// round 2
// baseline (speedup 1.0000x reference)
#include <cuda_runtime.h>
#include <math.h>

#define D_MODEL 1024
#define T_TOK   4096      // B*S = 2*2048
#define H_FF    4096
#define N_HEAD  16
#define HEAD_DIM 64
#define SEQ     2048

// ---------------- scratch (no allocations allowed) ----------------
__device__ float g_ln  [T_TOK * D_MODEL];
__device__ float g_q   [T_TOK * D_MODEL];
__device__ float g_k   [T_TOK * D_MODEL];
__device__ float g_v   [T_TOK * D_MODEL];
__device__ float g_ctx [T_TOK * D_MODEL];
__device__ float g_res1[T_TOK * D_MODEL];
__device__ float g_ln2 [T_TOK * D_MODEL];
__device__ float g_h   [T_TOK * H_FF];

// ---------------- helpers ----------------
__device__ __forceinline__ float gelu_f(float x) {
    const float c = 0.7978845608028654f; // sqrt(2/pi)
    float t = tanhf(c * (x + 0.044715f * x * x * x));
    return 0.5f * x * (1.0f + t);
}

__device__ __forceinline__ float block_reduce_sum(float v, float* red) {
    int lane = threadIdx.x & 31;
    int wid  = threadIdx.x >> 5;
    #pragma unroll
    for (int o = 16; o > 0; o >>= 1) v += __shfl_down_sync(0xffffffffu, v, o);
    if (lane == 0) red[wid] = v;
    __syncthreads();
    float s = 0.f;
    if (wid == 0) {
        s = (lane < (blockDim.x >> 5)) ? red[lane] : 0.f;
        #pragma unroll
        for (int o = 4; o > 0; o >>= 1) s += __shfl_down_sync(0xffffffffu, s, o);
        if (lane == 0) red[0] = s;
    }
    __syncthreads();
    s = red[0];
    __syncthreads();
    return s;
}

// ---------------- LayerNorm (ddof=1) ----------------
__global__ __launch_bounds__(256)
void ln_kernel(const float* __restrict__ in, const float* __restrict__ sc,
               const float* __restrict__ sh, float* __restrict__ out) {
    __shared__ float red[32];
    int row = blockIdx.x;
    const float* xr = in + (size_t)row * D_MODEL;
    float* orow = out + (size_t)row * D_MODEL;
    int tid = threadIdx.x;

    float v[4];
    float s = 0.f;
    #pragma unroll
    for (int i = 0; i < 4; i++) { v[i] = xr[tid + 256 * i]; s += v[i]; }
    float total = block_reduce_sum(s, red);
    float mean = total * (1.0f / D_MODEL);

    float sq = 0.f;
    #pragma unroll
    for (int i = 0; i < 4; i++) { float d = v[i] - mean; sq += d * d; }
    float tsq = block_reduce_sum(sq, red);
    float var = tsq * (1.0f / (D_MODEL - 1));   // unbiased, torch default
    float rstd = rsqrtf(var + 1e-5f);

    #pragma unroll
    for (int i = 0; i < 4; i++) {
        int col = tid + 256 * i;
        orow[col] = (v[i] - mean) * rstd * sc[col] + sh[col];
    }
}

// ---------------- SGEMM: C[M,N] = A[M,K] * B[K,N] (+ epilogue) ----------------
// epi: 0 = none, 1 = +bias +res, 2 = gelu(+bias)
#define BM 128
#define BN 128
#define BKK 8
__global__ __launch_bounds__(256)
void sgemm_kernel(const float* __restrict__ A, const float* __restrict__ B,
                  float* __restrict__ C, int M, int N, int K,
                  int epi, const float* __restrict__ bias,
                  const float* __restrict__ res) {
    __shared__ float As[BKK][BM];
    __shared__ float Bs[BKK][BN];

    int bx = blockIdx.x;   // N tile
    int by = blockIdx.y;   // M tile
    int tid = threadIdx.x;
    int tx = tid & 15;     // 0..15  (N dir)
    int ty = tid >> 4;     // 0..15  (M dir)

    const float* Ab = A + (size_t)by * BM * K;
    const float* Bb = B + (size_t)bx * BN;

    int arow = tid >> 1;          // 0..127
    int acol = (tid & 1) * 4;     // 0 or 4
    int brow = tid >> 5;          // 0..7
    int bcol = (tid & 31) * 4;    // 0..124

    float acc[8][8];
    #pragma unroll
    for (int i = 0; i < 8; i++)
        #pragma unroll
        for (int j = 0; j < 8; j++) acc[i][j] = 0.f;

    int ntiles = K / BKK;
    float4 aReg = *(const float4*)(Ab + (size_t)arow * K + acol);
    float4 bReg = *(const float4*)(Bb + (size_t)brow * N + bcol);

    for (int t = 0; t < ntiles; t++) {
        As[acol + 0][arow] = aReg.x;
        As[acol + 1][arow] = aReg.y;
        As[acol + 2][arow] = aReg.z;
        As[acol + 3][arow] = aReg.w;
        *(float4*)&Bs[brow][bcol] = bReg;
        __syncthreads();

        if (t + 1 < ntiles) {
            aReg = *(const float4*)(Ab + (size_t)arow * K + (t + 1) * BKK + acol);
            bReg = *(const float4*)(Bb + ((size_t)(t + 1) * BKK + brow) * N + bcol);
        }

        #pragma unroll
        for (int k = 0; k < BKK; k++) {
            float a[8], b[8];
            *(float4*)(a)     = *(float4*)&As[k][ty * 8];
            *(float4*)(a + 4) = *(float4*)&As[k][ty * 8 + 4];
            *(float4*)(b)     = *(float4*)&Bs[k][tx * 8];
            *(float4*)(b + 4) = *(float4*)&Bs[k][tx * 8 + 4];
            #pragma unroll
            for (int i = 0; i < 8; i++)
                #pragma unroll
                for (int j = 0; j < 8; j++)
                    acc[i][j] = fmaf(a[i], b[j], acc[i][j]);
        }
        __syncthreads();
    }

    int rowbase = by * BM + ty * 8;
    int colbase = bx * BN + tx * 8;
    #pragma unroll
    for (int i = 0; i < 8; i++) {
        size_t rowoff = (size_t)(rowbase + i) * N;
        #pragma unroll
        for (int j = 0; j < 8; j++) {
            int col = colbase + j;
            float c = acc[i][j];
            if (epi == 1)       c = c + bias[col] + res[rowoff + col];
            else if (epi == 2)  c = gelu_f(c + bias[col]);
            C[rowoff + col] = c;
        }
    }
}

// ---------------- Flash attention (fp32, causal) ----------------
// grid: (S/64, N_HEAD, B), 256 threads. Br=64 queries, Bc=32 keys per tile.
#define BR 64
#define BC 32
__global__ __launch_bounds__(256)
void attn_kernel(const float* __restrict__ Q, const float* __restrict__ K,
                 const float* __restrict__ V, float* __restrict__ O) {
    __shared__ float Qs[BR][64];
    __shared__ float KVs[BC][65];
    __shared__ float Ss[BR][33];
    __shared__ float alphaS[BR];
    __shared__ float lS[BR];

    int tid = threadIdx.x;
    int qt = blockIdx.x, h = blockIdx.y, b = blockIdx.z;
    size_t base = ((size_t)b * SEQ) * D_MODEL + h * HEAD_DIM;

    // load Q tile (64x64)
    #pragma unroll
    for (int i = 0; i < 4; i++) {
        int fid = tid + 256 * i;          // float4 id
        int r = fid >> 4;
        int d = (fid & 15) << 2;
        float4 qv = *(const float4*)(Q + base + (size_t)(qt * BR + r) * D_MODEL + d);
        *(float4*)&Qs[r][d] = qv;
    }

    // S mapping: 2 rows x 4 cols; PV mapping: 2 rows x 8 cols
    int r0 = (tid >> 3) * 2;          // 0,2,...,62
    int sc0 = (tid & 7) * 4;          // 0..28
    int pc0 = (tid & 7) * 8;          // 0..56

    float acc[2][8];
    #pragma unroll
    for (int i = 0; i < 2; i++)
        #pragma unroll
        for (int j = 0; j < 8; j++) acc[i][j] = 0.f;

    float m_r = -1e30f, l_r = 0.f;    // valid for tid < 64 only

    __syncthreads();

    int jt_max = 2 * qt + 1;
    for (int jt = 0; jt <= jt_max; jt++) {
        // load K tile (32x64)
        #pragma unroll
        for (int i = 0; i < 2; i++) {
            int fid = tid + 256 * i;
            int j = fid >> 4;
            int d = (fid & 15) << 2;
            float4 kv = *(const float4*)(K + base + (size_t)(jt * BC + j) * D_MODEL + d);
            KVs[j][d + 0] = kv.x; KVs[j][d + 1] = kv.y;
            KVs[j][d + 2] = kv.z; KVs[j][d + 3] = kv.w;
        }
        __syncthreads();

        // S = Q K^T / 8 with causal mask
        float s[2][4];
        #pragma unroll
        for (int i = 0; i < 2; i++)
            #pragma unroll
            for (int j = 0; j < 4; j++) s[i][j] = 0.f;
        #pragma unroll 8
        for (int d = 0; d < 64; d++) {
            float a0 = Qs[r0][d], a1 = Qs[r0 + 1][d];
            float b0 = KVs[sc0 + 0][d], b1 = KVs[sc0 + 1][d];
            float b2 = KVs[sc0 + 2][d], b3 = KVs[sc0 + 3][d];
            s[0][0] = fmaf(a0, b0, s[0][0]); s[0][1] = fmaf(a0, b1, s[0][1]);
            s[0][2] = fmaf(a0, b2, s[0][2]); s[0][3] = fmaf(a0, b3, s[0][3]);
            s[1][0] = fmaf(a1, b0, s[1][0]); s[1][1] = fmaf(a1, b1, s[1][1]);
            s[1][2] = fmaf(a1, b2, s[1][2]); s[1][3] = fmaf(a1, b3, s[1][3]);
        }
        #pragma unroll
        for (int i = 0; i < 2; i++) {
            int qi = qt * BR + r0 + i;
            #pragma unroll
            for (int j = 0; j < 4; j++) {
                int kj = jt * BC + sc0 + j;
                Ss[r0 + i][sc0 + j] = (kj > qi) ? -1e30f : s[i][j] * 0.125f;
            }
        }
        __syncthreads();

        // load V tile into KVs (S-compute done); softmax on rows (tid<64)
        #pragma unroll
        for (int i = 0; i < 2; i++) {
            int fid = tid + 256 * i;
            int j = fid >> 4;
            int d = (fid & 15) << 2;
            float4 vv = *(const float4*)(V + base + (size_t)(jt * BC + j) * D_MODEL + d);
            KVs[j][d + 0] = vv.x; KVs[j][d + 1] = vv.y;
            KVs[j][d + 2] = vv.z; KVs[j][d + 3] = vv.w;
        }
        if (tid < BR) {
            int row = tid;
            float mx = -1e30f;
            #pragma unroll 8
            for (int c = 0; c < BC; c++) mx = fmaxf(mx, Ss[row][c]);
            float m_new = fmaxf(m_r, mx);
            float alpha = expf(m_r - m_new);
            float lsum = 0.f;
            #pragma unroll 8
            for (int c = 0; c < BC; c++) {
                float p = expf(Ss[row][c] - m_new);
                Ss[row][c] = p;
                lsum += p;
            }
            l_r = l_r * alpha + lsum;
            m_r = m_new;
            alphaS[row] = alpha;
        }
        __syncthreads();

        // rescale + PV accumulate
        float al0 = alphaS[r0], al1 = alphaS[r0 + 1];
        #pragma unroll
        for (int j = 0; j < 8; j++) { acc[0][j] *= al0; acc[1][j] *= al1; }
        #pragma unroll 4
        for (int j = 0; j < BC; j++) {
            float p0 = Ss[r0][j], p1 = Ss[r0 + 1][j];
            #pragma unroll
            for (int c = 0; c < 8; c++) {
                float v = KVs[j][pc0 + c];
                acc[0][c] = fmaf(p0, v, acc[0][c]);
                acc[1][c] = fmaf(p1, v, acc[1][c]);
            }
        }
        __syncthreads();
    }

    if (tid < BR) lS[tid] = l_r;
    __syncthreads();

    float inv0 = 1.0f / lS[r0];
    float inv1 = 1.0f / lS[r0 + 1];
    #pragma unroll
    for (int i = 0; i < 2; i++) {
        float inv = (i == 0) ? inv0 : inv1;
        size_t orow = base + (size_t)(qt * BR + r0 + i) * D_MODEL + pc0;
        #pragma unroll
        for (int c = 0; c < 8; c++) O[orow + c] = acc[i][c] * inv;
    }
}

// ---------------- launch ----------------
extern "C" void kernel_launch(void* const* d_in, const int* in_sizes, int n_in,
                              void* d_out, int out_size) {
    const float* x         = (const float*)d_in[0];
    const float* ln1_scale = (const float*)d_in[1];
    const float* ln1_shift = (const float*)d_in[2];
    const float* wq        = (const float*)d_in[3];
    const float* wk        = (const float*)d_in[4];
    const float* wv        = (const float*)d_in[5];
    const float* w_out     = (const float*)d_in[6];
    const float* b_out     = (const float*)d_in[7];
    const float* ln2_scale = (const float*)d_in[8];
    const float* ln2_shift = (const float*)d_in[9];
    const float* w1        = (const float*)d_in[10];
    const float* b1        = (const float*)d_in[11];
    const float* w2        = (const float*)d_in[12];
    const float* b2        = (const float*)d_in[13];
    float* out = (float*)d_out;

    float *p_ln, *p_q, *p_k, *p_v, *p_ctx, *p_res1, *p_ln2, *p_h;
    cudaGetSymbolAddress((void**)&p_ln,   g_ln);
    cudaGetSymbolAddress((void**)&p_q,    g_q);
    cudaGetSymbolAddress((void**)&p_k,    g_k);
    cudaGetSymbolAddress((void**)&p_v,    g_v);
    cudaGetSymbolAddress((void**)&p_ctx,  g_ctx);
    cudaGetSymbolAddress((void**)&p_res1, g_res1);
    cudaGetSymbolAddress((void**)&p_ln2,  g_ln2);
    cudaGetSymbolAddress((void**)&p_h,    g_h);

    // 1. LN1
    ln_kernel<<<T_TOK, 256>>>(x, ln1_scale, ln1_shift, p_ln);

    // 2. QKV projections
    dim3 g1(D_MODEL / BN, T_TOK / BM);
    sgemm_kernel<<<g1, 256>>>(p_ln, wq, p_q, T_TOK, D_MODEL, D_MODEL, 0, nullptr, nullptr);
    sgemm_kernel<<<g1, 256>>>(p_ln, wk, p_k, T_TOK, D_MODEL, D_MODEL, 0, nullptr, nullptr);
    sgemm_kernel<<<g1, 256>>>(p_ln, wv, p_v, T_TOK, D_MODEL, D_MODEL, 0, nullptr, nullptr);

    // 3. causal attention
    dim3 ga(SEQ / BR, N_HEAD, 2);
    attn_kernel<<<ga, 256>>>(p_q, p_k, p_v, p_ctx);

    // 4. out projection + bias + residual(x)
    sgemm_kernel<<<g1, 256>>>(p_ctx, w_out, p_res1, T_TOK, D_MODEL, D_MODEL, 1, b_out, x);

    // 5. LN2
    ln_kernel<<<T_TOK, 256>>>(p_res1, ln2_scale, ln2_shift, p_ln2);

    // 6. MLP up + gelu
    dim3 g2(H_FF / BN, T_TOK / BM);
    sgemm_kernel<<<g2, 256>>>(p_ln2, w1, p_h, T_TOK, H_FF, D_MODEL, 2, b1, nullptr);

    // 7. MLP down + bias + residual(res1) -> out
    sgemm_kernel<<<g1, 256>>>(p_h, w2, out, T_TOK, D_MODEL, H_FF, 1, b2, p_res1);
}

// round 7
// speedup vs baseline: 1.6784x; 1.6784x over previous
#include <cuda_runtime.h>
#include <cuda_bf16.h>
#include <math.h>
#include <cstdint>

#define D_MODEL 1024
#define T_TOK   4096      // B*S
#define H_FF    4096
#define N_HEAD  16
#define HEAD_DIM 64
#define SEQ     2048

// ================= base-ISA PTX helpers (sm_103 base target — NO tcgen05) ====
__device__ __forceinline__ uint32_t smem_to_u32(const void* p) {
    uint32_t a;
    asm("{ .reg .u64 t; cvta.to.shared.u64 t, %1; cvt.u32.u64 %0, t; }" : "=r"(a) : "l"(p));
    return a;
}
__device__ __forceinline__ void cp16(uint32_t smem, const void* g) {
    asm volatile("cp.async.cg.shared.global [%0], [%1], 16;" :: "r"(smem), "l"(g));
}
__device__ __forceinline__ void ldsm_x4(uint32_t addr, uint32_t& r0, uint32_t& r1,
                                        uint32_t& r2, uint32_t& r3) {
    asm volatile("ldmatrix.sync.aligned.m8n8.x4.shared.b16 {%0,%1,%2,%3}, [%4];"
        : "=r"(r0), "=r"(r1), "=r"(r2), "=r"(r3) : "r"(addr));
}
__device__ __forceinline__ void mma16816(float* c, const uint32_t* a, uint32_t b0, uint32_t b1) {
    asm volatile(
        "mma.sync.aligned.m16n8k16.row.col.f32.bf16.bf16.f32 "
        "{%0,%1,%2,%3}, {%4,%5,%6,%7}, {%8,%9}, {%0,%1,%2,%3};"
        : "+f"(c[0]), "+f"(c[1]), "+f"(c[2]), "+f"(c[3])
        : "r"(a[0]), "r"(a[1]), "r"(a[2]), "r"(a[3]), "r"(b0), "r"(b1));
}

// ================= scratch =================
__device__ __align__(256) float g_q   [T_TOK * D_MODEL];
__device__ __align__(256) float g_k   [T_TOK * D_MODEL];
__device__ __align__(256) float g_v   [T_TOK * D_MODEL];
__device__ __align__(256) float g_res1[T_TOK * D_MODEL];
__device__ __align__(256) __nv_bfloat16 g_lnh [T_TOK * D_MODEL];
__device__ __align__(256) __nv_bfloat16 g_lnl [T_TOK * D_MODEL];
__device__ __align__(256) __nv_bfloat16 g_ctxh[T_TOK * D_MODEL];
__device__ __align__(256) __nv_bfloat16 g_ctxl[T_TOK * D_MODEL];
__device__ __align__(256) __nv_bfloat16 g_ln2h[T_TOK * D_MODEL];
__device__ __align__(256) __nv_bfloat16 g_ln2l[T_TOK * D_MODEL];
__device__ __align__(256) __nv_bfloat16 g_hh  [T_TOK * H_FF];
__device__ __align__(256) __nv_bfloat16 g_hl  [T_TOK * H_FF];
__device__ __align__(256) __nv_bfloat16 g_wqh [D_MODEL * D_MODEL];
__device__ __align__(256) __nv_bfloat16 g_wql [D_MODEL * D_MODEL];
__device__ __align__(256) __nv_bfloat16 g_wkh [D_MODEL * D_MODEL];
__device__ __align__(256) __nv_bfloat16 g_wkl [D_MODEL * D_MODEL];
__device__ __align__(256) __nv_bfloat16 g_wvh [D_MODEL * D_MODEL];
__device__ __align__(256) __nv_bfloat16 g_wvl [D_MODEL * D_MODEL];
__device__ __align__(256) __nv_bfloat16 g_woh [D_MODEL * D_MODEL];
__device__ __align__(256) __nv_bfloat16 g_wol [D_MODEL * D_MODEL];
__device__ __align__(256) __nv_bfloat16 g_w1h [H_FF * D_MODEL];
__device__ __align__(256) __nv_bfloat16 g_w1l [H_FF * D_MODEL];
__device__ __align__(256) __nv_bfloat16 g_w2h [D_MODEL * H_FF];
__device__ __align__(256) __nv_bfloat16 g_w2l [D_MODEL * H_FF];

// ================= helpers =================
__device__ __forceinline__ float gelu_f(float x) {
    const float c = 0.7978845608028654f;
    float t = tanhf(c * (x + 0.044715f * x * x * x));
    return 0.5f * x * (1.0f + t);
}
__device__ __forceinline__ void split_bf(float v, __nv_bfloat16& hi, __nv_bfloat16& lo) {
    hi = __float2bfloat16(v);
    lo = __float2bfloat16(v - __bfloat162float(hi));
}
__device__ __forceinline__ float block_reduce_sum(float v, float* red) {
    int lane = threadIdx.x & 31;
    int wid  = threadIdx.x >> 5;
    #pragma unroll
    for (int o = 16; o > 0; o >>= 1) v += __shfl_down_sync(0xffffffffu, v, o);
    if (lane == 0) red[wid] = v;
    __syncthreads();
    float s = 0.f;
    if (wid == 0) {
        s = (lane < (blockDim.x >> 5)) ? red[lane] : 0.f;
        #pragma unroll
        for (int o = 4; o > 0; o >>= 1) s += __shfl_down_sync(0xffffffffu, s, o);
        if (lane == 0) red[0] = s;
    }
    __syncthreads();
    s = red[0];
    __syncthreads();
    return s;
}

// ================= LayerNorm (ddof=1) -> bf16 hi/lo =================
__global__ __launch_bounds__(256)
void ln_kernel(const float* __restrict__ in, const float* __restrict__ sc,
               const float* __restrict__ sh,
               __nv_bfloat16* __restrict__ oh, __nv_bfloat16* __restrict__ ol) {
    __shared__ float red[32];
    int row = blockIdx.x;
    const float* xr = in + (size_t)row * D_MODEL;
    int tid = threadIdx.x;

    float v[4];
    float s = 0.f;
    #pragma unroll
    for (int i = 0; i < 4; i++) { v[i] = xr[tid + 256 * i]; s += v[i]; }
    float total = block_reduce_sum(s, red);
    float mean = total * (1.0f / D_MODEL);

    float sq = 0.f;
    #pragma unroll
    for (int i = 0; i < 4; i++) { float d = v[i] - mean; sq += d * d; }
    float tsq = block_reduce_sum(sq, red);
    float rstd = rsqrtf(tsq * (1.0f / (D_MODEL - 1)) + 1e-5f);

    size_t ro = (size_t)row * D_MODEL;
    #pragma unroll
    for (int i = 0; i < 4; i++) {
        int col = tid + 256 * i;
        float y = (v[i] - mean) * rstd * sc[col] + sh[col];
        __nv_bfloat16 hi, lo; split_bf(y, hi, lo);
        oh[ro + col] = hi; ol[ro + col] = lo;
    }
}

// ================= weight transpose + split: W[K,N] -> Wt[N,K] bf16 hi/lo ====
__global__ __launch_bounds__(256)
void tsplit_kernel(const float* __restrict__ W, __nv_bfloat16* __restrict__ Th,
                   __nv_bfloat16* __restrict__ Tl, int K, int N) {
    __shared__ float t[32][33];
    int n0 = blockIdx.x * 32, k0 = blockIdx.y * 32;
    int tx = threadIdx.x & 31, ty = threadIdx.x >> 5;  // 32 x 8
    #pragma unroll
    for (int i = 0; i < 4; i++) {
        int k = k0 + ty + 8 * i;
        t[ty + 8 * i][tx] = W[(size_t)k * N + n0 + tx];
    }
    __syncthreads();
    #pragma unroll
    for (int i = 0; i < 4; i++) {
        int n = n0 + ty + 8 * i;
        int k = k0 + tx;
        float v = t[tx][ty + 8 * i];
        __nv_bfloat16 hi, lo; split_bf(v, hi, lo);
        Th[(size_t)n * K + k] = hi;
        Tl[(size_t)n * K + k] = lo;
    }
}

// ================= mma.sync bf16-split GEMM ==================================
// C[M,N] = A*B^T, A = Ahi+Alo ([M,K] bf16), B = Bhi+Blo ([N,K] bf16)
// 3 passes accumulated in registers: Ahi*Bhi + Ahi*Blo + Alo*Bhi.
// epi: 0 = fp32 C; 1 = C = acc + bias + res; 2 = gelu(acc+bias) -> Ohi/Olo bf16
#define GS_TOTAL 65536   // A0(16K) B0(16K) A1(16K) B1(16K)

__global__ __launch_bounds__(256, 2)
void gemm_mma(const __nv_bfloat16* __restrict__ Ahi, const __nv_bfloat16* __restrict__ Alo,
              const __nv_bfloat16* __restrict__ Bhi, const __nv_bfloat16* __restrict__ Blo,
              float* __restrict__ C,
              __nv_bfloat16* __restrict__ Ohi, __nv_bfloat16* __restrict__ Olo,
              int N, int K, int epi,
              const float* __restrict__ bias, const float* __restrict__ res) {
    extern __shared__ char smem[];
    uint32_t sbase = smem_to_u32(smem);
    int tid = threadIdx.x, lane = tid & 31, wid = tid >> 5;
    int bx = blockIdx.x, by = blockIdx.y;
    int wm = (wid >> 2) * 64;   // warp M offset (2 warps in M)
    int wn = (wid & 3) * 32;    // warp N offset (4 warps in N)

    float acc[4][4][4];
    #pragma unroll
    for (int i = 0; i < 4; i++)
        #pragma unroll
        for (int j = 0; j < 4; j++)
            #pragma unroll
            for (int e = 0; e < 4; e++) acc[i][j][e] = 0.f;

    const int KC = K >> 6;          // 64-element K chunks per pass
    const int T = 3 * KC;
    size_t arow0 = (size_t)by * 128;
    size_t brow0 = (size_t)bx * 128;

    auto load_chunk = [&](int t, int buf) {
        int p = (t >= 2 * KC) ? 2 : ((t >= KC) ? 1 : 0);
        int kc = t - p * KC;
        const __nv_bfloat16* Ap = (p == 2) ? Alo : Ahi;
        const __nv_bfloat16* Bp = (p == 1) ? Blo : Bhi;
        size_t kofs = (size_t)kc * 64;
        uint32_t abase = sbase + buf * 32768u;
        uint32_t bbase = abase + 16384u;
        #pragma unroll
        for (int i = 0; i < 4; i++) {
            int f = tid + 256 * i;
            int row = f >> 3;
            int cg  = f & 7;
            uint32_t off = row * 128 + cg * 16;
            uint32_t sw = off ^ ((off >> 3) & 0x70);
            cp16(abase + sw, Ap + (arow0 + row) * K + kofs + cg * 8);
            cp16(bbase + sw, Bp + (brow0 + row) * K + kofs + cg * 8);
        }
    };

    load_chunk(0, 0);
    asm volatile("cp.async.commit_group;" ::: "memory");

    for (int t = 0; t < T; t++) {
        if (t + 1 < T) {
            load_chunk(t + 1, (t + 1) & 1);
            asm volatile("cp.async.commit_group;" ::: "memory");
            asm volatile("cp.async.wait_group 1;" ::: "memory");
        } else {
            asm volatile("cp.async.wait_group 0;" ::: "memory");
        }
        __syncthreads();

        uint32_t abase = sbase + (t & 1) * 32768u;
        uint32_t bbase = abase + 16384u;
        #pragma unroll
        for (int ks = 0; ks < 4; ks++) {
            int k0b = ks * 32;              // byte offset of k-step in 128B row
            uint32_t a[4][4];
            #pragma unroll
            for (int mi = 0; mi < 4; mi++) {
                int row = wm + mi * 16 + (lane & 15);
                uint32_t off = row * 128 + k0b + ((lane >> 4) << 4);
                uint32_t sw = off ^ ((off >> 3) & 0x70);
                ldsm_x4(abase + sw, a[mi][0], a[mi][1], a[mi][2], a[mi][3]);
            }
            uint32_t b[4][2];
            #pragma unroll
            for (int nj2 = 0; nj2 < 2; nj2++) {
                int g = lane >> 3, lr = lane & 7;
                int nrow = wn + nj2 * 16 + ((g >> 1) << 3) + lr;
                uint32_t off = nrow * 128 + k0b + ((g & 1) << 4);
                uint32_t sw = off ^ ((off >> 3) & 0x70);
                uint32_t r0, r1, r2, r3;
                ldsm_x4(bbase + sw, r0, r1, r2, r3);
                b[nj2 * 2 + 0][0] = r0; b[nj2 * 2 + 0][1] = r1;
                b[nj2 * 2 + 1][0] = r2; b[nj2 * 2 + 1][1] = r3;
            }
            #pragma unroll
            for (int mi = 0; mi < 4; mi++)
                #pragma unroll
                for (int nj = 0; nj < 4; nj++)
                    mma16816(acc[mi][nj], a[mi], b[nj][0], b[nj][1]);
        }
        __syncthreads();
    }

    // ---------------- epilogue (registers -> gmem) ----------------
    int r_in = lane >> 2;
    int c_in = (lane & 3) * 2;
    #pragma unroll
    for (int mi = 0; mi < 4; mi++) {
        #pragma unroll
        for (int half = 0; half < 2; half++) {
            int grow = by * 128 + wm + mi * 16 + r_in + half * 8;
            size_t rowoff = (size_t)grow * N;
            #pragma unroll
            for (int nj = 0; nj < 4; nj++) {
                int gcol = bx * 128 + wn + nj * 8 + c_in;
                float v0 = acc[mi][nj][half * 2 + 0];
                float v1 = acc[mi][nj][half * 2 + 1];
                if (epi == 0) {
                    *(float2*)(C + rowoff + gcol) = make_float2(v0, v1);
                } else if (epi == 1) {
                    float2 bi = *(const float2*)(bias + gcol);
                    float2 rs = *(const float2*)(res + rowoff + gcol);
                    *(float2*)(C + rowoff + gcol) = make_float2(v0 + bi.x + rs.x, v1 + bi.y + rs.y);
                } else {
                    float2 bi = *(const float2*)(bias + gcol);
                    float gx0 = gelu_f(v0 + bi.x);
                    float gx1 = gelu_f(v1 + bi.y);
                    __nv_bfloat16 h0, l0, h1, l1;
                    split_bf(gx0, h0, l0); split_bf(gx1, h1, l1);
                    __nv_bfloat162 hv; hv.x = h0; hv.y = h1;
                    __nv_bfloat162 lv; lv.x = l0; lv.y = l1;
                    *(__nv_bfloat162*)(Ohi + rowoff + gcol) = hv;
                    *(__nv_bfloat162*)(Olo + rowoff + gcol) = lv;
                }
            }
        }
    }
}

// ================= Flash attention (fp32, causal) -> bf16 hi/lo ctx ==========
#define BR 64
#define BC 32
__global__ __launch_bounds__(256)
void attn_kernel(const float* __restrict__ Q, const float* __restrict__ K,
                 const float* __restrict__ V,
                 __nv_bfloat16* __restrict__ OHi, __nv_bfloat16* __restrict__ OLo) {
    __shared__ float Qs[BR][64];
    __shared__ float KVs[BC][65];
    __shared__ float Ss[BR][33];
    __shared__ float alphaS[BR];
    __shared__ float lS[BR];

    int tid = threadIdx.x;
    int qt = blockIdx.x, h = blockIdx.y, b = blockIdx.z;
    size_t base = ((size_t)b * SEQ) * D_MODEL + h * HEAD_DIM;

    #pragma unroll
    for (int i = 0; i < 4; i++) {
        int fid = tid + 256 * i;
        int r = fid >> 4;
        int d = (fid & 15) << 2;
        float4 qv = *(const float4*)(Q + base + (size_t)(qt * BR + r) * D_MODEL + d);
        *(float4*)&Qs[r][d] = qv;
    }

    int r0 = (tid >> 3) * 2;
    int sc0 = (tid & 7) * 4;
    int pc0 = (tid & 7) * 8;

    float acc[2][8];
    #pragma unroll
    for (int i = 0; i < 2; i++)
        #pragma unroll
        for (int j = 0; j < 8; j++) acc[i][j] = 0.f;

    float m_r = -1e30f, l_r = 0.f;
    __syncthreads();

    int jt_max = 2 * qt + 1;
    for (int jt = 0; jt <= jt_max; jt++) {
        #pragma unroll
        for (int i = 0; i < 2; i++) {
            int fid = tid + 256 * i;
            int j = fid >> 4;
            int d = (fid & 15) << 2;
            float4 kv = *(const float4*)(K + base + (size_t)(jt * BC + j) * D_MODEL + d);
            KVs[j][d + 0] = kv.x; KVs[j][d + 1] = kv.y;
            KVs[j][d + 2] = kv.z; KVs[j][d + 3] = kv.w;
        }
        __syncthreads();

        float s[2][4];
        #pragma unroll
        for (int i = 0; i < 2; i++)
            #pragma unroll
            for (int j = 0; j < 4; j++) s[i][j] = 0.f;
        #pragma unroll 8
        for (int d = 0; d < 64; d++) {
            float a0 = Qs[r0][d], a1 = Qs[r0 + 1][d];
            float b0 = KVs[sc0 + 0][d], b1 = KVs[sc0 + 1][d];
            float b2 = KVs[sc0 + 2][d], b3 = KVs[sc0 + 3][d];
            s[0][0] = fmaf(a0, b0, s[0][0]); s[0][1] = fmaf(a0, b1, s[0][1]);
            s[0][2] = fmaf(a0, b2, s[0][2]); s[0][3] = fmaf(a0, b3, s[0][3]);
            s[1][0] = fmaf(a1, b0, s[1][0]); s[1][1] = fmaf(a1, b1, s[1][1]);
            s[1][2] = fmaf(a1, b2, s[1][2]); s[1][3] = fmaf(a1, b3, s[1][3]);
        }
        #pragma unroll
        for (int i = 0; i < 2; i++) {
            int qi = qt * BR + r0 + i;
            #pragma unroll
            for (int j = 0; j < 4; j++) {
                int kj = jt * BC + sc0 + j;
                Ss[r0 + i][sc0 + j] = (kj > qi) ? -1e30f : s[i][j] * 0.125f;
            }
        }
        __syncthreads();

        #pragma unroll
        for (int i = 0; i < 2; i++) {
            int fid = tid + 256 * i;
            int j = fid >> 4;
            int d = (fid & 15) << 2;
            float4 vv = *(const float4*)(V + base + (size_t)(jt * BC + j) * D_MODEL + d);
            KVs[j][d + 0] = vv.x; KVs[j][d + 1] = vv.y;
            KVs[j][d + 2] = vv.z; KVs[j][d + 3] = vv.w;
        }
        if (tid < BR) {
            int row = tid;
            float mx = -1e30f;
            #pragma unroll 8
            for (int c = 0; c < BC; c++) mx = fmaxf(mx, Ss[row][c]);
            float m_new = fmaxf(m_r, mx);
            float alpha = expf(m_r - m_new);
            float lsum = 0.f;
            #pragma unroll 8
            for (int c = 0; c < BC; c++) {
                float p = expf(Ss[row][c] - m_new);
                Ss[row][c] = p;
                lsum += p;
            }
            l_r = l_r * alpha + lsum;
            m_r = m_new;
            alphaS[row] = alpha;
        }
        __syncthreads();

        float al0 = alphaS[r0], al1 = alphaS[r0 + 1];
        #pragma unroll
        for (int j = 0; j < 8; j++) { acc[0][j] *= al0; acc[1][j] *= al1; }
        #pragma unroll 4
        for (int j = 0; j < BC; j++) {
            float p0 = Ss[r0][j], p1 = Ss[r0 + 1][j];
            #pragma unroll
            for (int c = 0; c < 8; c++) {
                float v = KVs[j][pc0 + c];
                acc[0][c] = fmaf(p0, v, acc[0][c]);
                acc[1][c] = fmaf(p1, v, acc[1][c]);
            }
        }
        __syncthreads();
    }

    if (tid < BR) lS[tid] = l_r;
    __syncthreads();

    float inv0 = 1.0f / lS[r0];
    float inv1 = 1.0f / lS[r0 + 1];
    #pragma unroll
    for (int i = 0; i < 2; i++) {
        float inv = (i == 0) ? inv0 : inv1;
        size_t orow = base + (size_t)(qt * BR + r0 + i) * D_MODEL + pc0;
        #pragma unroll
        for (int c = 0; c < 8; c++) {
            float v = acc[i][c] * inv;
            __nv_bfloat16 hi, lo; split_bf(v, hi, lo);
            OHi[orow + c] = hi; OLo[orow + c] = lo;
        }
    }
}

// ================= launch =================
extern "C" void kernel_launch(void* const* d_in, const int* in_sizes, int n_in,
                              void* d_out, int out_size) {
    const float* x         = (const float*)d_in[0];
    const float* ln1_scale = (const float*)d_in[1];
    const float* ln1_shift = (const float*)d_in[2];
    const float* wq        = (const float*)d_in[3];
    const float* wk        = (const float*)d_in[4];
    const float* wv        = (const float*)d_in[5];
    const float* w_out     = (const float*)d_in[6];
    const float* b_out     = (const float*)d_in[7];
    const float* ln2_scale = (const float*)d_in[8];
    const float* ln2_shift = (const float*)d_in[9];
    const float* w1        = (const float*)d_in[10];
    const float* b1        = (const float*)d_in[11];
    const float* w2        = (const float*)d_in[12];
    const float* b2        = (const float*)d_in[13];
    float* out = (float*)d_out;

    float *p_q, *p_k, *p_v, *p_res1;
    __nv_bfloat16 *p_lnh, *p_lnl, *p_ctxh, *p_ctxl, *p_ln2h, *p_ln2l, *p_hh, *p_hl;
    __nv_bfloat16 *p_wqh, *p_wql, *p_wkh, *p_wkl, *p_wvh, *p_wvl, *p_woh, *p_wol;
    __nv_bfloat16 *p_w1h, *p_w1l, *p_w2h, *p_w2l;
    cudaGetSymbolAddress((void**)&p_q,    g_q);
    cudaGetSymbolAddress((void**)&p_k,    g_k);
    cudaGetSymbolAddress((void**)&p_v,    g_v);
    cudaGetSymbolAddress((void**)&p_res1, g_res1);
    cudaGetSymbolAddress((void**)&p_lnh,  g_lnh);
    cudaGetSymbolAddress((void**)&p_lnl,  g_lnl);
    cudaGetSymbolAddress((void**)&p_ctxh, g_ctxh);
    cudaGetSymbolAddress((void**)&p_ctxl, g_ctxl);
    cudaGetSymbolAddress((void**)&p_ln2h, g_ln2h);
    cudaGetSymbolAddress((void**)&p_ln2l, g_ln2l);
    cudaGetSymbolAddress((void**)&p_hh,   g_hh);
    cudaGetSymbolAddress((void**)&p_hl,   g_hl);
    cudaGetSymbolAddress((void**)&p_wqh,  g_wqh);
    cudaGetSymbolAddress((void**)&p_wql,  g_wql);
    cudaGetSymbolAddress((void**)&p_wkh,  g_wkh);
    cudaGetSymbolAddress((void**)&p_wkl,  g_wkl);
    cudaGetSymbolAddress((void**)&p_wvh,  g_wvh);
    cudaGetSymbolAddress((void**)&p_wvl,  g_wvl);
    cudaGetSymbolAddress((void**)&p_woh,  g_woh);
    cudaGetSymbolAddress((void**)&p_wol,  g_wol);
    cudaGetSymbolAddress((void**)&p_w1h,  g_w1h);
    cudaGetSymbolAddress((void**)&p_w1l,  g_w1l);
    cudaGetSymbolAddress((void**)&p_w2h,  g_w2h);
    cudaGetSymbolAddress((void**)&p_w2l,  g_w2l);

    cudaFuncSetAttribute(gemm_mma, cudaFuncAttributeMaxDynamicSharedMemorySize, GS_TOTAL);

    // weight transpose+split
    dim3 tsb(256);
    tsplit_kernel<<<dim3(D_MODEL / 32, D_MODEL / 32), tsb>>>(wq,    p_wqh, p_wql, D_MODEL, D_MODEL);
    tsplit_kernel<<<dim3(D_MODEL / 32, D_MODEL / 32), tsb>>>(wk,    p_wkh, p_wkl, D_MODEL, D_MODEL);
    tsplit_kernel<<<dim3(D_MODEL / 32, D_MODEL / 32), tsb>>>(wv,    p_wvh, p_wvl, D_MODEL, D_MODEL);
    tsplit_kernel<<<dim3(D_MODEL / 32, D_MODEL / 32), tsb>>>(w_out, p_woh, p_wol, D_MODEL, D_MODEL);
    tsplit_kernel<<<dim3(H_FF / 32,    D_MODEL / 32), tsb>>>(w1,    p_w1h, p_w1l, D_MODEL, H_FF);
    tsplit_kernel<<<dim3(D_MODEL / 32, H_FF / 32),    tsb>>>(w2,    p_w2h, p_w2l, H_FF, D_MODEL);

    // LN1
    ln_kernel<<<T_TOK, 256>>>(x, ln1_scale, ln1_shift, p_lnh, p_lnl);

    // QKV
    dim3 gD(D_MODEL / 128, T_TOK / 128);
    gemm_mma<<<gD, 256, GS_TOTAL>>>(p_lnh, p_lnl, p_wqh, p_wql, p_q, nullptr, nullptr,
                                    D_MODEL, D_MODEL, 0, nullptr, nullptr);
    gemm_mma<<<gD, 256, GS_TOTAL>>>(p_lnh, p_lnl, p_wkh, p_wkl, p_k, nullptr, nullptr,
                                    D_MODEL, D_MODEL, 0, nullptr, nullptr);
    gemm_mma<<<gD, 256, GS_TOTAL>>>(p_lnh, p_lnl, p_wvh, p_wvl, p_v, nullptr, nullptr,
                                    D_MODEL, D_MODEL, 0, nullptr, nullptr);

    // attention -> ctx hi/lo
    dim3 ga(SEQ / BR, N_HEAD, 2);
    attn_kernel<<<ga, 256>>>(p_q, p_k, p_v, p_ctxh, p_ctxl);

    // out projection + bias + residual(x) -> res1 (fp32)
    gemm_mma<<<gD, 256, GS_TOTAL>>>(p_ctxh, p_ctxl, p_woh, p_wol, p_res1, nullptr, nullptr,
                                    D_MODEL, D_MODEL, 1, b_out, x);

    // LN2
    ln_kernel<<<T_TOK, 256>>>(p_res1, ln2_scale, ln2_shift, p_ln2h, p_ln2l);

    // MLP up + gelu -> h hi/lo
    dim3 gF(H_FF / 128, T_TOK / 128);
    gemm_mma<<<gF, 256, GS_TOTAL>>>(p_ln2h, p_ln2l, p_w1h, p_w1l, nullptr, p_hh, p_hl,
                                    H_FF, D_MODEL, 2, b1, nullptr);

    // MLP down + bias + residual(res1) -> out
    gemm_mma<<<gD, 256, GS_TOTAL>>>(p_hh, p_hl, p_w2h, p_w2l, out, nullptr, nullptr,
                                    D_MODEL, H_FF, 1, b2, p_res1);
}